// round 13
// baseline (speedup 1.0000x reference)
#include <cuda_runtime.h>
#include <cuda_fp16.h>
#include <cstdint>

// Problem constants (fixed by the dataset).
#define NN 50000
#define EE 800000
#define HH 256

// ---------------------------------------------------------------------------
// Device scratch (static allocation; no cudaMalloc allowed)
// ---------------------------------------------------------------------------
__device__ int    g_deg[NN];
__device__ int    g_cursor[NN];
__device__ int    g_rowptr[NN + 1];
__device__ int    g_colidx[EE];
__device__ int    g_bsums[64];
__device__ int    g_maxdeg;
__device__ float  g_diag[NN];
__device__ float  g_negscale;
__device__ float  g_T3[(size_t)NN * 3];          // tx1 scratch (3 channels)
__device__ __half g_Yh[(size_t)NN * HH];         // y activations (fp16)
__device__ __half g_Hh[(size_t)NN * HH];         // hidden activations (fp16)
__device__ __half g_Th[(size_t)NN * HH];         // tx1 activations (fp16)
__device__ __half g_Wh[(size_t)6 * 256 * 512];   // fused transposed fp16 weights [l][n][k]

static __device__ __forceinline__ uint32_t smem_u32(const void* p) {
    uint32_t a;
    asm("{ .reg .u64 t; cvta.to.shared.u64 t, %1; cvt.u32.u64 %0, t; }"
        : "=r"(a) : "l"(p));
    return a;
}

static __device__ __forceinline__ void mma_f16(float* d,
                                               const uint32_t* a,
                                               uint32_t b0, uint32_t b1) {
    asm volatile("mma.sync.aligned.m16n8k16.row.col.f32.f16.f16.f32 "
                 "{%0,%1,%2,%3}, {%4,%5,%6,%7}, {%8,%9}, {%0,%1,%2,%3};"
                 : "+f"(d[0]), "+f"(d[1]), "+f"(d[2]), "+f"(d[3])
                 : "r"(a[0]), "r"(a[1]), "r"(a[2]), "r"(a[3]),
                   "r"(b0), "r"(b1));
}

#define LDM_X4(r0, r1, r2, r3, addr)                                           \
    asm volatile("ldmatrix.sync.aligned.m8n8.x4.shared.b16 {%0,%1,%2,%3}, [%4];" \
                 : "=r"(r0), "=r"(r1), "=r"(r2), "=r"(r3) : "r"(addr))

#define CP_ASYNC16(dst, src, sz)                                               \
    asm volatile("cp.async.cg.shared.global [%0], [%1], 16, %2;"               \
                 :: "r"(dst), "l"(src), "r"(sz))
#define CP_COMMIT() asm volatile("cp.async.commit_group;" ::: "memory")

// PDL: primary signals dependents may launch; secondary waits for primary grid.
#define GDC_LAUNCH_DEPENDENTS() asm volatile("griddepcontrol.launch_dependents;")
#define GDC_WAIT()              asm volatile("griddepcontrol.wait;" ::: "memory")

// ---------------------------------------------------------------------------
// Setup kernels: degree, lambda_max, coefficients, CSR build
// ---------------------------------------------------------------------------
__global__ void zero_k() {
    int i = blockIdx.x * blockDim.x + threadIdx.x;
    if (i < NN) { g_deg[i] = 0; g_cursor[i] = 0; }
    if (i == 0) g_maxdeg = 0;
}

__global__ void degree_k(const int* __restrict__ row) {
    int e = blockIdx.x * blockDim.x + threadIdx.x;
    if (e < EE) atomicAdd(&g_deg[row[e]], 1);
}

__global__ void maxdeg_k() {
    int i = blockIdx.x * blockDim.x + threadIdx.x;
    if (i < NN) atomicMax(&g_maxdeg, g_deg[i]);
}

__global__ void coeff_k() {
    int i = blockIdx.x * blockDim.x + threadIdx.x;
    if (i < NN) {
        float md    = (float)g_maxdeg;
        float lam   = 2.0f * md;
        float scale = 2.0f / lam;
        g_diag[i]   = scale * (float)g_deg[i] - 1.0f;
        if (i == 0) g_negscale = -scale;
    }
}

#define SCAN_B 1024
__global__ void scan_block_k() {
    __shared__ int sh[SCAN_B];
    int tid = threadIdx.x;
    int i = blockIdx.x * SCAN_B + tid;
    int v = (i < NN) ? g_deg[i] : 0;
    sh[tid] = v;
    __syncthreads();
    for (int off = 1; off < SCAN_B; off <<= 1) {
        int t = (tid >= off) ? sh[tid - off] : 0;
        __syncthreads();
        sh[tid] += t;
        __syncthreads();
    }
    if (i < NN) g_rowptr[i] = sh[tid] - v;
    if (tid == SCAN_B - 1) g_bsums[blockIdx.x] = sh[tid];
}

__global__ void scan_sums_k(int nb) {
    __shared__ int sh[64];
    int tid = threadIdx.x;
    int v = (tid < nb) ? g_bsums[tid] : 0;
    sh[tid] = v;
    __syncthreads();
    for (int off = 1; off < 64; off <<= 1) {
        int t = (tid >= off) ? sh[tid - off] : 0;
        __syncthreads();
        sh[tid] += t;
        __syncthreads();
    }
    if (tid < nb) g_bsums[tid] = sh[tid] - v;
}

__global__ void scan_add_k() {
    int i = blockIdx.x * SCAN_B + threadIdx.x;
    if (i < NN) g_rowptr[i] += g_bsums[blockIdx.x];
    if (i == 0) g_rowptr[NN] = EE;
}

__global__ void scatter_k(const int* __restrict__ row, const int* __restrict__ col) {
    int e = blockIdx.x * blockDim.x + threadIdx.x;
    if (e < EE) {
        int r = row[e];
        int p = atomicAdd(&g_cursor[r], 1);
        g_colidx[g_rowptr[r] + p] = col[e];
    }
}

// Build fused transposed fp16 weights: g_Wh[l][n][k] = (k<256?Wr0:Wr1)[l][k%256][n]
__global__ void wt16_k(const float* __restrict__ Wr0, const float* __restrict__ Wr1) {
    size_t i = (size_t)blockIdx.x * blockDim.x + threadIdx.x;
    if (i >= (size_t)6 * 256 * 512) return;
    int k = (int)(i & 511);
    int n = (int)((i >> 9) & 255);
    int l = (int)(i >> 17);
    float v = (k < 256) ? Wr0[(size_t)l * 65536 + (size_t)k * 256 + n]
                        : Wr1[(size_t)l * 65536 + (size_t)(k - 256) * 256 + n];
    g_Wh[i] = __float2half_rn(v);
}

// ---------------------------------------------------------------------------
// Aggregation + tx1, fp16 features. PERSISTENT grid (single wave, 4 blocks/SM)
// so griddepcontrol.launch_dependents fires at kernel START across all blocks,
// letting the PDL-launched GEMM overlap its X-half with this kernel.
// Each 256-thread block handles 2 nodes per loop iteration.
// ---------------------------------------------------------------------------
#define AGG_GRID 592   // 148 SMs x 4 blocks (single wave)

__global__ void agg256h_k(const __half2* __restrict__ X2, __half2* __restrict__ T2) {
    GDC_LAUNCH_DEPENDENTS();
    int half = threadIdx.x >> 7;      // 0/1 -> node within pair
    int c    = threadIdx.x & 127;     // half2 channel index
    for (int pair = blockIdx.x; pair * 2 < NN; pair += AGG_GRID) {
        int i = pair * 2 + half;
        if (i >= NN) continue;
        int s = g_rowptr[i];
        int e = g_rowptr[i + 1];
        float sx = 0.f, sy = 0.f;
        int k = s;
        for (; k + 4 <= e; k += 4) {
            int j0 = g_colidx[k + 0];
            int j1 = g_colidx[k + 1];
            int j2 = g_colidx[k + 2];
            int j3 = g_colidx[k + 3];
            float2 f0 = __half22float2(__ldg(&X2[(size_t)j0 * 128 + c]));
            float2 f1 = __half22float2(__ldg(&X2[(size_t)j1 * 128 + c]));
            float2 f2 = __half22float2(__ldg(&X2[(size_t)j2 * 128 + c]));
            float2 f3 = __half22float2(__ldg(&X2[(size_t)j3 * 128 + c]));
            sx += (f0.x + f1.x) + (f2.x + f3.x);
            sy += (f0.y + f1.y) + (f2.y + f3.y);
        }
        for (; k < e; k++) {
            float2 f = __half22float2(__ldg(&X2[(size_t)g_colidx[k] * 128 + c]));
            sx += f.x;
            sy += f.y;
        }
        float2 xi = __half22float2(X2[(size_t)i * 128 + c]);
        float ns = g_negscale, d = g_diag[i];
        T2[(size_t)i * 128 + c] = __floats2half2_rn(ns * sx + d * xi.x, ns * sy + d * xi.y);
    }
}

// Aggregation + tx1 for C=3 (input layer, fp32): one thread per node.
__global__ void agg3_k(const float* __restrict__ X) {
    int i = blockIdx.x * blockDim.x + threadIdx.x;
    if (i >= NN) return;
    int s = g_rowptr[i];
    int e = g_rowptr[i + 1];
    float s0 = 0.f, s1 = 0.f, s2 = 0.f;
    for (int k = s; k < e; k++) {
        int j = g_colidx[k];
        s0 += X[j * 3 + 0];
        s1 += X[j * 3 + 1];
        s2 += X[j * 3 + 2];
    }
    float d = g_diag[i], ns = g_negscale;
    g_T3[i * 3 + 0] = ns * s0 + d * X[i * 3 + 0];
    g_T3[i * 3 + 1] = ns * s1 + d * X[i * 3 + 1];
    g_T3[i * 3 + 2] = ns * s2 + d * X[i * 3 + 2];
}

// ---------------------------------------------------------------------------
// Input cheb: Yh = fp16( relu(x @ Wi0 + tx1_3 @ Wi1 + bi) )
// ---------------------------------------------------------------------------
__global__ void input_gemm_k(const float* __restrict__ X,
                             const float* __restrict__ Wi0,
                             const float* __restrict__ Wi1,
                             const float* __restrict__ bi,
                             __half* __restrict__ Y) {
    int c = threadIdx.x;
    float w00 = Wi0[0 * HH + c], w01 = Wi0[1 * HH + c], w02 = Wi0[2 * HH + c];
    float w10 = Wi1[0 * HH + c], w11 = Wi1[1 * HH + c], w12 = Wi1[2 * HH + c];
    float b = bi[c];
    const int npb = (NN + gridDim.x - 1) / gridDim.x;
    int i0 = blockIdx.x * npb;
    int i1 = min(i0 + npb, NN);
    for (int i = i0; i < i1; i++) {
        float x0 = X[i * 3 + 0], x1 = X[i * 3 + 1], x2 = X[i * 3 + 2];
        float t0 = g_T3[i * 3 + 0], t1 = g_T3[i * 3 + 1], t2 = g_T3[i * 3 + 2];
        float v = x0 * w00 + x1 * w01 + x2 * w02
                + t0 * w10 + t1 * w11 + t2 * w12 + b;
        Y[(size_t)i * HH + c] = __float2half_rn(fmaxf(v, 0.0f));
    }
}

// ---------------------------------------------------------------------------
// fp16 mma GEMM, cp.async 4-stage pipeline + ldmatrix fragments, PDL-aware:
//   C = epilogue( [A1 | g_Th] @ Wh^T + bias ),  all activations fp16.
// K-chunks 0-7 read A1 (ready before the preceding agg even starts); chunks
// 8-15 read g_Th (agg output) -> griddepcontrol.wait is placed exactly before
// the first stage-8 cp.async issue (end of mainloop iteration c==5).
// BM=BN=128, BK=32, 4 stages, 256 threads, 2 CTAs/SM (80 KB smem).
// MODE 0: relu(acc+bias); MODE 1: 0.5*(R + relu(acc+bias)) (R==C alias OK).
// ---------------------------------------------------------------------------
#define AH_STRIDE 40   // halves per row (32 + 8 pad); 80 B
#define AH_TILE   (128 * AH_STRIDE)     // 5120 halves per stage per operand
#define NSTAGE    4
#define GEMM_SMEM (2 * NSTAGE * AH_TILE * 2)   // 81920 B

template <int MODE>
__global__ void __launch_bounds__(256)
gemm_f16_k(const __half* __restrict__ A1,
           const __half* __restrict__ Wh,
           const float* __restrict__ bias,
           __half* __restrict__ C,
           const __half* __restrict__ R) {
    extern __shared__ __half smh[];
    const uint32_t sb    = smem_u32(smh);
    const uint32_t aBase = sb;                                 // 4 A stages
    const uint32_t bBase = sb + NSTAGE * AH_TILE * 2;          // 4 B stages

    const int tid    = threadIdx.x;
    const int lane   = tid & 31;
    const int wid    = tid >> 5;
    const int warp_m = wid >> 2;          // 0..1 -> 64-row slab
    const int warp_n = wid & 3;           // 0..3 -> 32-col slab
    const int g      = lane >> 2;         // 0..7
    const int cc     = lane & 3;          // 0..3
    const int mBase  = blockIdx.x * 128;
    const int nBase  = blockIdx.y * 128;

    // ldmatrix per-lane byte offset: rows lane%16, col-block lane/16 (8 halves)
    const uint32_t lmOff = ((uint32_t)(lane & 15) * AH_STRIDE + (uint32_t)(lane >> 4) * 8) * 2;

    float acc[4][4][4];
#pragma unroll
    for (int mt = 0; mt < 4; mt++)
#pragma unroll
        for (int nt = 0; nt < 4; nt++)
#pragma unroll
            for (int q = 0; q < 4; q++) acc[mt][nt][q] = 0.0f;

    // per-thread cp.async coordinates: 2 x 16B each for A and B per stage
    const int ldR = tid >> 2;             // 0..63 (p adds 64)
    const int ldQ = (tid & 3) * 8;        // halves offset (16 B quanta)

    auto issue_stage = [&](int c) {
        const int s = c & (NSTAGE - 1);
        const __half* asrc = (c < 8) ? A1 : (const __half*)g_Th;
        const int kel = (c & 7) * 32;
#pragma unroll
        for (int p = 0; p < 2; p++) {
            int r  = ldR + p * 64;
            int gr = mBase + r;
            int ok = (gr < NN);
            const __half* src = asrc + (size_t)(ok ? gr : 0) * 256 + kel + ldQ;
            uint32_t dst = aBase + (uint32_t)(s * AH_TILE + r * AH_STRIDE + ldQ) * 2;
            CP_ASYNC16(dst, src, ok ? 16 : 0);   // zero-fill OOB rows
        }
        const int kg = c * 32;
#pragma unroll
        for (int p = 0; p < 2; p++) {
            int n = ldR + p * 64;
            const __half* src = Wh + (size_t)(nBase + n) * 512 + kg + ldQ;
            uint32_t dst = bBase + (uint32_t)(s * AH_TILE + n * AH_STRIDE + ldQ) * 2;
            CP_ASYNC16(dst, src, 16);
        }
        CP_COMMIT();
    };

    issue_stage(0);
    issue_stage(1);
    issue_stage(2);

    for (int c = 0; c < 16; c++) {
        const int s = c & (NSTAGE - 1);
        // ensure stage c landed: pending groups must drop to min(2, 15-c)
        if (c < 14)      asm volatile("cp.async.wait_group 2;" ::: "memory");
        else if (c == 14) asm volatile("cp.async.wait_group 1;" ::: "memory");
        else              asm volatile("cp.async.wait_group 0;" ::: "memory");
        __syncthreads();

        const uint32_t aS = aBase + (uint32_t)(s * AH_TILE) * 2;
        const uint32_t bS = bBase + (uint32_t)(s * AH_TILE) * 2;
#pragma unroll
        for (int ks = 0; ks < 2; ks++) {
            const uint32_t koB = (uint32_t)(ks * 16) * 2;   // bytes
            uint32_t a[4][4];
#pragma unroll
            for (int mt = 0; mt < 4; mt++) {
                uint32_t ad = aS + (uint32_t)((warp_m * 64 + mt * 16) * AH_STRIDE) * 2
                            + koB + lmOff;
                LDM_X4(a[mt][0], a[mt][1], a[mt][2], a[mt][3], ad);
            }
            uint32_t b2[2][4];
#pragma unroll
            for (int pr = 0; pr < 2; pr++) {
                uint32_t bd = bS + (uint32_t)((warp_n * 32 + pr * 16) * AH_STRIDE) * 2
                            + koB + lmOff;
                LDM_X4(b2[pr][0], b2[pr][1], b2[pr][2], b2[pr][3], bd);
            }
#pragma unroll
            for (int mt = 0; mt < 4; mt++)
#pragma unroll
                for (int nt = 0; nt < 4; nt++)
                    mma_f16(acc[mt][nt], a[mt],
                            b2[nt >> 1][nt & 1], b2[nt >> 1][(nt & 1) + 2]);
        }

        if (c == 5) GDC_WAIT();               // agg output needed from stage 8 on
        if (c + 3 < 16) issue_stage(c + 3);   // writes stage (c-1)%4: safe post-sync
    }

    // ---- epilogue: bias + relu (+ residual average), fp16 store ----
#pragma unroll
    for (int mt = 0; mt < 4; mt++) {
        int r0 = mBase + warp_m * 64 + mt * 16 + g;
#pragma unroll
        for (int nt = 0; nt < 4; nt++) {
            int n0 = nBase + warp_n * 32 + nt * 8 + 2 * cc;
            float2 bv = *(const float2*)&bias[n0];
            if (r0 < NN) {
                float ox = fmaxf(acc[mt][nt][0] + bv.x, 0.f);
                float oy = fmaxf(acc[mt][nt][1] + bv.y, 0.f);
                if (MODE == 1) {
                    float2 rr = __half22float2(*(const __half2*)&R[(size_t)r0 * 256 + n0]);
                    ox = 0.5f * (ox + rr.x);
                    oy = 0.5f * (oy + rr.y);
                }
                *(__half2*)&C[(size_t)r0 * 256 + n0] = __floats2half2_rn(ox, oy);
            }
            int r1 = r0 + 8;
            if (r1 < NN) {
                float ox = fmaxf(acc[mt][nt][2] + bv.x, 0.f);
                float oy = fmaxf(acc[mt][nt][3] + bv.y, 0.f);
                if (MODE == 1) {
                    float2 rr = __half22float2(*(const __half2*)&R[(size_t)r1 * 256 + n0]);
                    ox = 0.5f * (ox + rr.x);
                    oy = 0.5f * (oy + rr.y);
                }
                *(__half2*)&C[(size_t)r1 * 256 + n0] = __floats2half2_rn(ox, oy);
            }
        }
    }
}

// ---------------------------------------------------------------------------
// Final cheb: y2 = Y @ Wf0 + g_Th @ Wf1 + bf, and writes fp32 y (fused copy).
// ---------------------------------------------------------------------------
__global__ void final_k(const __half2* __restrict__ Y2,
                        const float* __restrict__ Wf0,
                        const float* __restrict__ Wf1,
                        const float* __restrict__ bf,
                        float* __restrict__ out,
                        float2* __restrict__ outY2) {
    int warp = threadIdx.x >> 5;
    int lane = threadIdx.x & 31;
    int node = blockIdx.x * (blockDim.x >> 5) + warp;
    if (node >= NN) return;
    const __half2* T2 = (const __half2*)g_Th;

    float a0 = 0.f, a1 = 0.f, a2 = 0.f;
    for (int k2 = lane; k2 < 128; k2 += 32) {
        float2 yv = __half22float2(Y2[(size_t)node * 128 + k2]);
        float2 tv = __half22float2(T2[(size_t)node * 128 + k2]);
        outY2[(size_t)node * 128 + k2] = yv;
        int k = 2 * k2;
        a0 += yv.x * Wf0[k * 3 + 0] + yv.y * Wf0[(k + 1) * 3 + 0]
            + tv.x * Wf1[k * 3 + 0] + tv.y * Wf1[(k + 1) * 3 + 0];
        a1 += yv.x * Wf0[k * 3 + 1] + yv.y * Wf0[(k + 1) * 3 + 1]
            + tv.x * Wf1[k * 3 + 1] + tv.y * Wf1[(k + 1) * 3 + 1];
        a2 += yv.x * Wf0[k * 3 + 2] + yv.y * Wf0[(k + 1) * 3 + 2]
            + tv.x * Wf1[k * 3 + 2] + tv.y * Wf1[(k + 1) * 3 + 2];
    }
#pragma unroll
    for (int o = 16; o > 0; o >>= 1) {
        a0 += __shfl_xor_sync(0xffffffffu, a0, o);
        a1 += __shfl_xor_sync(0xffffffffu, a1, o);
        a2 += __shfl_xor_sync(0xffffffffu, a2, o);
    }
    if (lane == 0) {
        out[node * 3 + 0] = a0 + bf[0];
        out[node * 3 + 1] = a1 + bf[1];
        out[node * 3 + 2] = a2 + bf[2];
    }
}

// ---------------------------------------------------------------------------
// Launch: single stream. GEMMs use PDL (programmatic stream serialization)
// so they overlap their X-half with the preceding persistent agg kernel.
// Fallback to a plain launch if cudaLaunchKernelEx errors.
// ---------------------------------------------------------------------------
extern "C" void kernel_launch(void* const* d_in, const int* in_sizes, int n_in,
                              void* d_out, int out_size) {
    const float* x   = (const float*)d_in[0];
    const int*   ei  = (const int*)d_in[1];
    const float* Wi0 = (const float*)d_in[2];
    const float* Wi1 = (const float*)d_in[3];
    const float* bi  = (const float*)d_in[4];
    const float* Wr0 = (const float*)d_in[5];
    const float* Wr1 = (const float*)d_in[6];
    const float* br  = (const float*)d_in[7];
    const float* Wf0 = (const float*)d_in[8];
    const float* Wf1 = (const float*)d_in[9];
    const float* bf  = (const float*)d_in[10];

    float* out  = (float*)d_out;
    float* outY = out + (size_t)NN * 3;

    const int* row = ei;
    const int* col = ei + EE;

    __half *dYh = nullptr, *dHh = nullptr, *dTh = nullptr, *dWh = nullptr;
    cudaGetSymbolAddress((void**)&dYh, g_Yh);
    cudaGetSymbolAddress((void**)&dHh, g_Hh);
    cudaGetSymbolAddress((void**)&dTh, g_Th);
    cudaGetSymbolAddress((void**)&dWh, g_Wh);

    cudaFuncSetAttribute(gemm_f16_k<0>, cudaFuncAttributeMaxDynamicSharedMemorySize, GEMM_SMEM);
    cudaFuncSetAttribute(gemm_f16_k<1>, cudaFuncAttributeMaxDynamicSharedMemorySize, GEMM_SMEM);

    const int nTB = (NN + 255) / 256;
    const int eTB = (EE + 255) / 256;
    const int nb  = (NN + SCAN_B - 1) / SCAN_B;
    dim3 gg((NN + 127) / 128, 2);

    // PDL launch helper for the GEMMs.
    auto launch_gemm = [&](void (*kfn)(const __half*, const __half*, const float*,
                                       __half*, const __half*),
                           const __half* A, const __half* W, const float* b,
                           __half* C, const __half* R) {
        cudaLaunchConfig_t cfg = {};
        cfg.gridDim = gg;
        cfg.blockDim = dim3(256, 1, 1);
        cfg.dynamicSmemBytes = GEMM_SMEM;
        cfg.stream = 0;
        cudaLaunchAttribute at[1];
        at[0].id = cudaLaunchAttributeProgrammaticStreamSerialization;
        at[0].val.programmaticStreamSerializationAllowed = 1;
        cfg.attrs = at;
        cfg.numAttrs = 1;
        if (cudaLaunchKernelEx(&cfg, kfn, A, W, b, C, R) != cudaSuccess) {
            kfn<<<gg, 256, GEMM_SMEM>>>(A, W, b, C, R);   // sequential fallback
        }
    };

    // --- graph setup: degree, coefficients, CSR, fp16 weights ---
    zero_k<<<nTB, 256>>>();
    degree_k<<<eTB, 256>>>(row);
    maxdeg_k<<<nTB, 256>>>();
    coeff_k<<<nTB, 256>>>();
    scan_block_k<<<nb, SCAN_B>>>();
    scan_sums_k<<<1, 64>>>(nb);
    scan_add_k<<<nb, SCAN_B>>>();
    scatter_k<<<eTB, 256>>>(row, col);
    wt16_k<<<3072, 256>>>(Wr0, Wr1);

    // --- input layer ---
    agg3_k<<<nTB, 256>>>(x);
    input_gemm_k<<<400, 256>>>(x, Wi0, Wi1, bi, dYh);

    // --- residual blocks: persistent agg -> PDL gemm (X-half overlapped) ---
    for (int i = 0; i < 3; i++) {
        const __half* Wa = dWh + (size_t)(2 * i) * 256 * 512;
        const float*  ba = br  + (size_t)(2 * i) * HH;
        const __half* Wb = dWh + (size_t)(2 * i + 1) * 256 * 512;
        const float*  bb = br  + (size_t)(2 * i + 1) * HH;

        agg256h_k<<<AGG_GRID, 256>>>((const __half2*)dYh, (__half2*)dTh);
        launch_gemm(gemm_f16_k<0>, dYh, Wa, ba, dHh, nullptr);
        agg256h_k<<<AGG_GRID, 256>>>((const __half2*)dHh, (__half2*)dTh);
        launch_gemm(gemm_f16_k<1>, dHh, Wb, bb, dYh, dYh);
    }

    // --- final layer (y2 + fused fp32 y copy) ---
    agg256h_k<<<AGG_GRID, 256>>>((const __half2*)dYh, (__half2*)dTh);
    final_k<<<(NN + 3) / 4, 128>>>((const __half2*)dYh, Wf0, Wf1, bf, out, (float2*)outY);
}

// round 14
// speedup vs baseline: 1.1403x; 1.1403x over previous
#include <cuda_runtime.h>
#include <cuda_fp16.h>
#include <cstdint>

// Problem constants (fixed by the dataset).
#define NN 50000
#define EE 800000
#define HH 256

// ---------------------------------------------------------------------------
// Device scratch (static allocation; no cudaMalloc allowed)
// ---------------------------------------------------------------------------
__device__ int    g_deg[NN];
__device__ int    g_cursor[NN];
__device__ int    g_rowptr[NN + 1];
__device__ int    g_colidx[EE];
__device__ int    g_bsums[64];
__device__ int    g_maxdeg;
__device__ float  g_T3[(size_t)NN * 3];          // tx1 scratch (3 channels)
__device__ __half g_Yh[(size_t)NN * HH];         // y activations (fp16)
__device__ __half g_Hh[(size_t)NN * HH];         // hidden activations (fp16)
__device__ __half g_Th[(size_t)NN * HH];         // tx1 activations (fp16)
__device__ __half g_Wh[(size_t)6 * 256 * 512];   // fused transposed fp16 weights [l][n][k]

static __device__ __forceinline__ uint32_t smem_u32(const void* p) {
    uint32_t a;
    asm("{ .reg .u64 t; cvta.to.shared.u64 t, %1; cvt.u32.u64 %0, t; }"
        : "=r"(a) : "l"(p));
    return a;
}

static __device__ __forceinline__ void mma_f16(float* d,
                                               const uint32_t* a,
                                               uint32_t b0, uint32_t b1) {
    asm volatile("mma.sync.aligned.m16n8k16.row.col.f32.f16.f16.f32 "
                 "{%0,%1,%2,%3}, {%4,%5,%6,%7}, {%8,%9}, {%0,%1,%2,%3};"
                 : "+f"(d[0]), "+f"(d[1]), "+f"(d[2]), "+f"(d[3])
                 : "r"(a[0]), "r"(a[1]), "r"(a[2]), "r"(a[3]),
                   "r"(b0), "r"(b1));
}

#define LDM_X4(r0, r1, r2, r3, addr)                                           \
    asm volatile("ldmatrix.sync.aligned.m8n8.x4.shared.b16 {%0,%1,%2,%3}, [%4];" \
                 : "=r"(r0), "=r"(r1), "=r"(r2), "=r"(r3) : "r"(addr))

#define CP_ASYNC16(dst, src, sz)                                               \
    asm volatile("cp.async.cg.shared.global [%0], [%1], 16, %2;"               \
                 :: "r"(dst), "l"(src), "r"(sz))
#define CP_COMMIT() asm volatile("cp.async.commit_group;" ::: "memory")

// ---------------------------------------------------------------------------
// Setup kernels: degree, lambda_max, CSR build
// ---------------------------------------------------------------------------
__global__ void zero_k() {
    int i = blockIdx.x * blockDim.x + threadIdx.x;
    if (i < NN) { g_deg[i] = 0; g_cursor[i] = 0; }
    if (i == 0) g_maxdeg = 0;
}

__global__ void degree_k(const int* __restrict__ row) {
    int e = blockIdx.x * blockDim.x + threadIdx.x;
    if (e < EE) atomicAdd(&g_deg[row[e]], 1);
}

__global__ void maxdeg_k() {
    int i = blockIdx.x * blockDim.x + threadIdx.x;
    if (i < NN) atomicMax(&g_maxdeg, g_deg[i]);
}

#define SCAN_B 1024
__global__ void scan_block_k() {
    __shared__ int sh[SCAN_B];
    int tid = threadIdx.x;
    int i = blockIdx.x * SCAN_B + tid;
    int v = (i < NN) ? g_deg[i] : 0;
    sh[tid] = v;
    __syncthreads();
    for (int off = 1; off < SCAN_B; off <<= 1) {
        int t = (tid >= off) ? sh[tid - off] : 0;
        __syncthreads();
        sh[tid] += t;
        __syncthreads();
    }
    if (i < NN) g_rowptr[i] = sh[tid] - v;
    if (tid == SCAN_B - 1) g_bsums[blockIdx.x] = sh[tid];
}

__global__ void scan_sums_k(int nb) {
    __shared__ int sh[64];
    int tid = threadIdx.x;
    int v = (tid < nb) ? g_bsums[tid] : 0;
    sh[tid] = v;
    __syncthreads();
    for (int off = 1; off < 64; off <<= 1) {
        int t = (tid >= off) ? sh[tid - off] : 0;
        __syncthreads();
        sh[tid] += t;
        __syncthreads();
    }
    if (tid < nb) g_bsums[tid] = sh[tid] - v;
}

__global__ void scan_add_k() {
    int i = blockIdx.x * SCAN_B + threadIdx.x;
    if (i < NN) g_rowptr[i] += g_bsums[blockIdx.x];
    if (i == 0) g_rowptr[NN] = EE;
}

__global__ void scatter_k(const int* __restrict__ row, const int* __restrict__ col) {
    int e = blockIdx.x * blockDim.x + threadIdx.x;
    if (e < EE) {
        int r = row[e];
        int p = atomicAdd(&g_cursor[r], 1);
        g_colidx[g_rowptr[r] + p] = col[e];
    }
}

// Build fused transposed fp16 weights: g_Wh[l][n][k] = (k<256?Wr0:Wr1)[l][k%256][n]
__global__ void wt16_k(const float* __restrict__ Wr0, const float* __restrict__ Wr1) {
    size_t i = (size_t)blockIdx.x * blockDim.x + threadIdx.x;
    if (i >= (size_t)6 * 256 * 512) return;
    int k = (int)(i & 511);
    int n = (int)((i >> 9) & 255);
    int l = (int)(i >> 17);
    float v = (k < 256) ? Wr0[(size_t)l * 65536 + (size_t)k * 256 + n]
                        : Wr1[(size_t)l * 65536 + (size_t)(k - 256) * 256 + n];
    g_Wh[i] = __float2half_rn(v);
}

// ---------------------------------------------------------------------------
// Aggregation + tx1, fp16 features: TWO nodes per 256-thread block.
// diag/negscale computed inline from g_deg/g_maxdeg (coeff_k removed):
//   scale = 2/(2*maxdeg) = 1/maxdeg;  diag = deg*scale - 1;  negscale = -scale
// ---------------------------------------------------------------------------
__global__ void agg256h_k(const __half2* __restrict__ X2, __half2* __restrict__ T2) {
    int i = blockIdx.x * 2 + (threadIdx.x >> 7);
    int c = threadIdx.x & 127;        // half2 channel index
    if (i >= NN) return;
    int s = g_rowptr[i];
    int e = g_rowptr[i + 1];
    float sx = 0.f, sy = 0.f;
    int k = s;
    for (; k + 4 <= e; k += 4) {
        int j0 = g_colidx[k + 0];
        int j1 = g_colidx[k + 1];
        int j2 = g_colidx[k + 2];
        int j3 = g_colidx[k + 3];
        float2 f0 = __half22float2(__ldg(&X2[(size_t)j0 * 128 + c]));
        float2 f1 = __half22float2(__ldg(&X2[(size_t)j1 * 128 + c]));
        float2 f2 = __half22float2(__ldg(&X2[(size_t)j2 * 128 + c]));
        float2 f3 = __half22float2(__ldg(&X2[(size_t)j3 * 128 + c]));
        sx += (f0.x + f1.x) + (f2.x + f3.x);
        sy += (f0.y + f1.y) + (f2.y + f3.y);
    }
    for (; k < e; k++) {
        float2 f = __half22float2(__ldg(&X2[(size_t)g_colidx[k] * 128 + c]));
        sx += f.x;
        sy += f.y;
    }
    float scale = 1.0f / (float)g_maxdeg;
    float d  = (float)(e - s) * scale - 1.0f;
    float ns = -scale;
    float2 xi = __half22float2(X2[(size_t)i * 128 + c]);
    T2[(size_t)i * 128 + c] = __floats2half2_rn(ns * sx + d * xi.x, ns * sy + d * xi.y);
}

// Aggregation + tx1 for C=3 (input layer, fp32): one thread per node.
__global__ void agg3_k(const float* __restrict__ X) {
    int i = blockIdx.x * blockDim.x + threadIdx.x;
    if (i >= NN) return;
    int s = g_rowptr[i];
    int e = g_rowptr[i + 1];
    float s0 = 0.f, s1 = 0.f, s2 = 0.f;
    for (int k = s; k < e; k++) {
        int j = g_colidx[k];
        s0 += X[j * 3 + 0];
        s1 += X[j * 3 + 1];
        s2 += X[j * 3 + 2];
    }
    float scale = 1.0f / (float)g_maxdeg;
    float d  = (float)(e - s) * scale - 1.0f;
    float ns = -scale;
    g_T3[i * 3 + 0] = ns * s0 + d * X[i * 3 + 0];
    g_T3[i * 3 + 1] = ns * s1 + d * X[i * 3 + 1];
    g_T3[i * 3 + 2] = ns * s2 + d * X[i * 3 + 2];
}

// ---------------------------------------------------------------------------
// Input cheb: Yh = fp16( relu(x @ Wi0 + tx1_3 @ Wi1 + bi) )
// ---------------------------------------------------------------------------
__global__ void input_gemm_k(const float* __restrict__ X,
                             const float* __restrict__ Wi0,
                             const float* __restrict__ Wi1,
                             const float* __restrict__ bi,
                             __half* __restrict__ Y) {
    int c = threadIdx.x;
    float w00 = Wi0[0 * HH + c], w01 = Wi0[1 * HH + c], w02 = Wi0[2 * HH + c];
    float w10 = Wi1[0 * HH + c], w11 = Wi1[1 * HH + c], w12 = Wi1[2 * HH + c];
    float b = bi[c];
    const int npb = (NN + gridDim.x - 1) / gridDim.x;
    int i0 = blockIdx.x * npb;
    int i1 = min(i0 + npb, NN);
    for (int i = i0; i < i1; i++) {
        float x0 = X[i * 3 + 0], x1 = X[i * 3 + 1], x2 = X[i * 3 + 2];
        float t0 = g_T3[i * 3 + 0], t1 = g_T3[i * 3 + 1], t2 = g_T3[i * 3 + 2];
        float v = x0 * w00 + x1 * w01 + x2 * w02
                + t0 * w10 + t1 * w11 + t2 * w12 + b;
        Y[(size_t)i * HH + c] = __float2half_rn(fmaxf(v, 0.0f));
    }
}

// ---------------------------------------------------------------------------
// PERSISTENT fp16 mma GEMM, cp.async 4-stage pipeline + ldmatrix fragments:
//   C = epilogue( [A1 | g_Th] @ Wh^T + bias ),  all activations fp16.
// Fixed grid of 296 CTAs (2/SM, single wave); each CTA loops over the 782
// (m,n) tiles with stride 296, re-priming the pipeline per tile. Removes the
// ~0.3-wave quantization tail of the 782-CTA launch.
// MODE 0: relu(acc+bias); MODE 1: 0.5*(R + relu(acc+bias)) (R==C alias OK).
// ---------------------------------------------------------------------------
#define AH_STRIDE 40   // halves per row (32 + 8 pad); 80 B
#define AH_TILE   (128 * AH_STRIDE)     // 5120 halves per stage per operand
#define NSTAGE    4
#define GEMM_SMEM (2 * NSTAGE * AH_TILE * 2)   // 81920 B
#define GEMM_GRID 296                   // 148 SMs x 2 CTAs
#define M_TILES   ((NN + 127) / 128)    // 391
#define N_TILES   2
#define TOT_TILES (M_TILES * N_TILES)   // 782

template <int MODE>
__global__ void __launch_bounds__(256)
gemm_f16_k(const __half* __restrict__ A1,
           const __half* __restrict__ Wh,
           const float* __restrict__ bias,
           __half* __restrict__ C,
           const __half* __restrict__ R) {
    extern __shared__ __half smh[];
    const uint32_t sb    = smem_u32(smh);
    const uint32_t aBase = sb;                                 // 4 A stages
    const uint32_t bBase = sb + NSTAGE * AH_TILE * 2;          // 4 B stages

    const int tid    = threadIdx.x;
    const int lane   = tid & 31;
    const int wid    = tid >> 5;
    const int warp_m = wid >> 2;          // 0..1 -> 64-row slab
    const int warp_n = wid & 3;           // 0..3 -> 32-col slab
    const int g      = lane >> 2;         // 0..7
    const int cc     = lane & 3;          // 0..3

    const uint32_t lmOff = ((uint32_t)(lane & 15) * AH_STRIDE + (uint32_t)(lane >> 4) * 8) * 2;
    const int ldR = tid >> 2;             // 0..63 (p adds 64)
    const int ldQ = (tid & 3) * 8;        // halves offset (16 B quanta)

    for (int t = blockIdx.x; t < TOT_TILES; t += GEMM_GRID) {
        const int mBase = (t >> 1) * 128;
        const int nBase = (t & 1) * 128;

        float acc[4][4][4];
#pragma unroll
        for (int mt = 0; mt < 4; mt++)
#pragma unroll
            for (int nt = 0; nt < 4; nt++)
#pragma unroll
                for (int q = 0; q < 4; q++) acc[mt][nt][q] = 0.0f;

        auto issue_stage = [&](int c) {
            const int s = c & (NSTAGE - 1);
            const __half* asrc = (c < 8) ? A1 : (const __half*)g_Th;
            const int kel = (c & 7) * 32;
#pragma unroll
            for (int p = 0; p < 2; p++) {
                int r  = ldR + p * 64;
                int gr = mBase + r;
                int ok = (gr < NN);
                const __half* src = asrc + (size_t)(ok ? gr : 0) * 256 + kel + ldQ;
                uint32_t dst = aBase + (uint32_t)(s * AH_TILE + r * AH_STRIDE + ldQ) * 2;
                CP_ASYNC16(dst, src, ok ? 16 : 0);   // zero-fill OOB rows
            }
            const int kg = c * 32;
#pragma unroll
            for (int p = 0; p < 2; p++) {
                int n = ldR + p * 64;
                const __half* src = Wh + (size_t)(nBase + n) * 512 + kg + ldQ;
                uint32_t dst = bBase + (uint32_t)(s * AH_TILE + n * AH_STRIDE + ldQ) * 2;
                CP_ASYNC16(dst, src, 16);
            }
            CP_COMMIT();
        };

        issue_stage(0);
        issue_stage(1);
        issue_stage(2);

        for (int c = 0; c < 16; c++) {
            const int s = c & (NSTAGE - 1);
            if (c < 14)       asm volatile("cp.async.wait_group 2;" ::: "memory");
            else if (c == 14) asm volatile("cp.async.wait_group 1;" ::: "memory");
            else              asm volatile("cp.async.wait_group 0;" ::: "memory");
            __syncthreads();

            const uint32_t aS = aBase + (uint32_t)(s * AH_TILE) * 2;
            const uint32_t bS = bBase + (uint32_t)(s * AH_TILE) * 2;
#pragma unroll
            for (int ks = 0; ks < 2; ks++) {
                const uint32_t koB = (uint32_t)(ks * 16) * 2;   // bytes
                uint32_t a[4][4];
#pragma unroll
                for (int mt = 0; mt < 4; mt++) {
                    uint32_t ad = aS + (uint32_t)((warp_m * 64 + mt * 16) * AH_STRIDE) * 2
                                + koB + lmOff;
                    LDM_X4(a[mt][0], a[mt][1], a[mt][2], a[mt][3], ad);
                }
                uint32_t b2[2][4];
#pragma unroll
                for (int pr = 0; pr < 2; pr++) {
                    uint32_t bd = bS + (uint32_t)((warp_n * 32 + pr * 16) * AH_STRIDE) * 2
                                + koB + lmOff;
                    LDM_X4(b2[pr][0], b2[pr][1], b2[pr][2], b2[pr][3], bd);
                }
#pragma unroll
                for (int mt = 0; mt < 4; mt++)
#pragma unroll
                    for (int nt = 0; nt < 4; nt++)
                        mma_f16(acc[mt][nt], a[mt],
                                b2[nt >> 1][nt & 1], b2[nt >> 1][(nt & 1) + 2]);
            }

            if (c + 3 < 16) issue_stage(c + 3);   // writes stage (c-1)%4: safe post-sync
        }

        // ---- epilogue: bias + relu (+ residual average), fp16 store ----
#pragma unroll
        for (int mt = 0; mt < 4; mt++) {
            int r0 = mBase + warp_m * 64 + mt * 16 + g;
#pragma unroll
            for (int nt = 0; nt < 4; nt++) {
                int n0 = nBase + warp_n * 32 + nt * 8 + 2 * cc;
                float2 bv = *(const float2*)&bias[n0];
                if (r0 < NN) {
                    float ox = fmaxf(acc[mt][nt][0] + bv.x, 0.f);
                    float oy = fmaxf(acc[mt][nt][1] + bv.y, 0.f);
                    if (MODE == 1) {
                        float2 rr = __half22float2(*(const __half2*)&R[(size_t)r0 * 256 + n0]);
                        ox = 0.5f * (ox + rr.x);
                        oy = 0.5f * (oy + rr.y);
                    }
                    *(__half2*)&C[(size_t)r0 * 256 + n0] = __floats2half2_rn(ox, oy);
                }
                int r1 = r0 + 8;
                if (r1 < NN) {
                    float ox = fmaxf(acc[mt][nt][2] + bv.x, 0.f);
                    float oy = fmaxf(acc[mt][nt][3] + bv.y, 0.f);
                    if (MODE == 1) {
                        float2 rr = __half22float2(*(const __half2*)&R[(size_t)r1 * 256 + n0]);
                        ox = 0.5f * (ox + rr.x);
                        oy = 0.5f * (oy + rr.y);
                    }
                    *(__half2*)&C[(size_t)r1 * 256 + n0] = __floats2half2_rn(ox, oy);
                }
            }
        }
        __syncthreads();   // protect SMEM reuse across tile iterations
    }
}

// ---------------------------------------------------------------------------
// Final cheb: y2 = Y @ Wf0 + g_Th @ Wf1 + bf, and writes fp32 y (fused copy).
// ---------------------------------------------------------------------------
__global__ void final_k(const __half2* __restrict__ Y2,
                        const float* __restrict__ Wf0,
                        const float* __restrict__ Wf1,
                        const float* __restrict__ bf,
                        float* __restrict__ out,
                        float2* __restrict__ outY2) {
    int warp = threadIdx.x >> 5;
    int lane = threadIdx.x & 31;
    int node = blockIdx.x * (blockDim.x >> 5) + warp;
    if (node >= NN) return;
    const __half2* T2 = (const __half2*)g_Th;

    float a0 = 0.f, a1 = 0.f, a2 = 0.f;
    for (int k2 = lane; k2 < 128; k2 += 32) {
        float2 yv = __half22float2(Y2[(size_t)node * 128 + k2]);
        float2 tv = __half22float2(T2[(size_t)node * 128 + k2]);
        outY2[(size_t)node * 128 + k2] = yv;
        int k = 2 * k2;
        a0 += yv.x * Wf0[k * 3 + 0] + yv.y * Wf0[(k + 1) * 3 + 0]
            + tv.x * Wf1[k * 3 + 0] + tv.y * Wf1[(k + 1) * 3 + 0];
        a1 += yv.x * Wf0[k * 3 + 1] + yv.y * Wf0[(k + 1) * 3 + 1]
            + tv.x * Wf1[k * 3 + 1] + tv.y * Wf1[(k + 1) * 3 + 1];
        a2 += yv.x * Wf0[k * 3 + 2] + yv.y * Wf0[(k + 1) * 3 + 2]
            + tv.x * Wf1[k * 3 + 2] + tv.y * Wf1[(k + 1) * 3 + 2];
    }
#pragma unroll
    for (int o = 16; o > 0; o >>= 1) {
        a0 += __shfl_xor_sync(0xffffffffu, a0, o);
        a1 += __shfl_xor_sync(0xffffffffu, a1, o);
        a2 += __shfl_xor_sync(0xffffffffu, a2, o);
    }
    if (lane == 0) {
        out[node * 3 + 0] = a0 + bf[0];
        out[node * 3 + 1] = a1 + bf[1];
        out[node * 3 + 2] = a2 + bf[2];
    }
}

// ---------------------------------------------------------------------------
// Launch: strictly sequential on the capture stream.
// ---------------------------------------------------------------------------
extern "C" void kernel_launch(void* const* d_in, const int* in_sizes, int n_in,
                              void* d_out, int out_size) {
    const float* x   = (const float*)d_in[0];
    const int*   ei  = (const int*)d_in[1];
    const float* Wi0 = (const float*)d_in[2];
    const float* Wi1 = (const float*)d_in[3];
    const float* bi  = (const float*)d_in[4];
    const float* Wr0 = (const float*)d_in[5];
    const float* Wr1 = (const float*)d_in[6];
    const float* br  = (const float*)d_in[7];
    const float* Wf0 = (const float*)d_in[8];
    const float* Wf1 = (const float*)d_in[9];
    const float* bf  = (const float*)d_in[10];

    float* out  = (float*)d_out;
    float* outY = out + (size_t)NN * 3;

    const int* row = ei;
    const int* col = ei + EE;

    __half *dYh = nullptr, *dHh = nullptr, *dTh = nullptr, *dWh = nullptr;
    cudaGetSymbolAddress((void**)&dYh, g_Yh);
    cudaGetSymbolAddress((void**)&dHh, g_Hh);
    cudaGetSymbolAddress((void**)&dTh, g_Th);
    cudaGetSymbolAddress((void**)&dWh, g_Wh);

    cudaFuncSetAttribute(gemm_f16_k<0>, cudaFuncAttributeMaxDynamicSharedMemorySize, GEMM_SMEM);
    cudaFuncSetAttribute(gemm_f16_k<1>, cudaFuncAttributeMaxDynamicSharedMemorySize, GEMM_SMEM);

    const int nTB = (NN + 255) / 256;
    const int eTB = (EE + 255) / 256;
    const int nb  = (NN + SCAN_B - 1) / SCAN_B;
    const int aggB = (NN + 1) / 2;   // 2 nodes per agg block

    // --- graph setup: degree, CSR, fp16 weights ---
    zero_k<<<nTB, 256>>>();
    degree_k<<<eTB, 256>>>(row);
    maxdeg_k<<<nTB, 256>>>();
    scan_block_k<<<nb, SCAN_B>>>();
    scan_sums_k<<<1, 64>>>(nb);
    scan_add_k<<<nb, SCAN_B>>>();
    scatter_k<<<eTB, 256>>>(row, col);
    wt16_k<<<3072, 256>>>(Wr0, Wr1);

    // --- input layer ---
    agg3_k<<<nTB, 256>>>(x);
    input_gemm_k<<<400, 256>>>(x, Wi0, Wi1, bi, dYh);

    // --- residual blocks (persistent cp.async fp16 mma GEMMs) ---
    for (int i = 0; i < 3; i++) {
        const __half* Wa = dWh + (size_t)(2 * i) * 256 * 512;
        const float*  ba = br  + (size_t)(2 * i) * HH;
        const __half* Wb = dWh + (size_t)(2 * i + 1) * 256 * 512;
        const float*  bb = br  + (size_t)(2 * i + 1) * HH;

        agg256h_k<<<aggB, 256>>>((const __half2*)dYh, (__half2*)dTh);
        gemm_f16_k<0><<<GEMM_GRID, 256, GEMM_SMEM>>>(dYh, Wa, ba, dHh, nullptr);
        agg256h_k<<<aggB, 256>>>((const __half2*)dHh, (__half2*)dTh);
        gemm_f16_k<1><<<GEMM_GRID, 256, GEMM_SMEM>>>(dHh, Wb, bb, dYh, dYh);
    }

    // --- final layer (y2 + fused fp32 y copy) ---
    agg256h_k<<<aggB, 256>>>((const __half2*)dYh, (__half2*)dTh);
    final_k<<<(NN + 3) / 4, 128>>>((const __half2*)dYh, Wf0, Wf1, bf, out, (float2*)outY);
}

// round 15
// speedup vs baseline: 1.1439x; 1.0032x over previous
#include <cuda_runtime.h>
#include <cuda_fp16.h>
#include <cstdint>

// Problem constants (fixed by the dataset).
#define NN 50000
#define EE 800000
#define HH 256

// ---------------------------------------------------------------------------
// Device scratch (static allocation; no cudaMalloc allowed)
// g_deg is SELF-RESTORING: degree_k builds it, scatter_k drains it back to 0
// via atomicSub, so no zeroing kernel is needed and graph replays are
// deterministic (BSS starts it at 0). g_maxdeg is write-once (atomicMax
// idempotent across replays).
// ---------------------------------------------------------------------------
__device__ int    g_deg[NN];
__device__ int    g_rowptr[NN + 1];
__device__ int    g_colidx[EE];
__device__ int    g_bsums[64];
__device__ int    g_maxdeg;
__device__ float  g_T3[(size_t)NN * 3];          // tx1 scratch (3 channels)
__device__ __half g_Yh[(size_t)NN * HH];         // y activations (fp16)
__device__ __half g_Hh[(size_t)NN * HH];         // hidden activations (fp16)
__device__ __half g_Th[(size_t)NN * HH];         // tx1 activations (fp16)
__device__ __half g_Wh[(size_t)6 * 256 * 512];   // fused transposed fp16 weights [l][n][k]

static __device__ __forceinline__ uint32_t smem_u32(const void* p) {
    uint32_t a;
    asm("{ .reg .u64 t; cvta.to.shared.u64 t, %1; cvt.u32.u64 %0, t; }"
        : "=r"(a) : "l"(p));
    return a;
}

static __device__ __forceinline__ void mma_f16(float* d,
                                               const uint32_t* a,
                                               uint32_t b0, uint32_t b1) {
    asm volatile("mma.sync.aligned.m16n8k16.row.col.f32.f16.f16.f32 "
                 "{%0,%1,%2,%3}, {%4,%5,%6,%7}, {%8,%9}, {%0,%1,%2,%3};"
                 : "+f"(d[0]), "+f"(d[1]), "+f"(d[2]), "+f"(d[3])
                 : "r"(a[0]), "r"(a[1]), "r"(a[2]), "r"(a[3]),
                   "r"(b0), "r"(b1));
}

#define LDM_X4(r0, r1, r2, r3, addr)                                           \
    asm volatile("ldmatrix.sync.aligned.m8n8.x4.shared.b16 {%0,%1,%2,%3}, [%4];" \
                 : "=r"(r0), "=r"(r1), "=r"(r2), "=r"(r3) : "r"(addr))

#define CP_ASYNC16(dst, src, sz)                                               \
    asm volatile("cp.async.cg.shared.global [%0], [%1], 16, %2;"               \
                 :: "r"(dst), "l"(src), "r"(sz))
#define CP_COMMIT() asm volatile("cp.async.commit_group;" ::: "memory")

// ---------------------------------------------------------------------------
// Setup kernels: degree, lambda_max, CSR build
// ---------------------------------------------------------------------------
__global__ void degree_k(const int* __restrict__ row) {
    int e = blockIdx.x * blockDim.x + threadIdx.x;
    if (e < EE) atomicAdd(&g_deg[row[e]], 1);
}

__global__ void maxdeg_k() {
    int i = blockIdx.x * blockDim.x + threadIdx.x;
    if (i < NN) atomicMax(&g_maxdeg, g_deg[i]);
}

#define SCAN_B 1024
__global__ void scan_block_k() {
    __shared__ int sh[SCAN_B];
    int tid = threadIdx.x;
    int i = blockIdx.x * SCAN_B + tid;
    int v = (i < NN) ? g_deg[i] : 0;
    sh[tid] = v;
    __syncthreads();
    for (int off = 1; off < SCAN_B; off <<= 1) {
        int t = (tid >= off) ? sh[tid - off] : 0;
        __syncthreads();
        sh[tid] += t;
        __syncthreads();
    }
    if (i < NN) g_rowptr[i] = sh[tid] - v;
    if (tid == SCAN_B - 1) g_bsums[blockIdx.x] = sh[tid];
}

__global__ void scan_sums_k(int nb) {
    __shared__ int sh[64];
    int tid = threadIdx.x;
    int v = (tid < nb) ? g_bsums[tid] : 0;
    sh[tid] = v;
    __syncthreads();
    for (int off = 1; off < 64; off <<= 1) {
        int t = (tid >= off) ? sh[tid - off] : 0;
        __syncthreads();
        sh[tid] += t;
        __syncthreads();
    }
    if (tid < nb) g_bsums[tid] = sh[tid] - v;
}

__global__ void scan_add_k() {
    int i = blockIdx.x * SCAN_B + threadIdx.x;
    if (i < NN) g_rowptr[i] += g_bsums[blockIdx.x];
    if (i == 0) g_rowptr[NN] = EE;
}

// Scatter uses g_deg itself as a draining cursor: old = atomicSub -> slot
// old-1 in [0, deg). Leaves g_deg == 0 for the next launch.
__global__ void scatter_k(const int* __restrict__ row, const int* __restrict__ col) {
    int e = blockIdx.x * blockDim.x + threadIdx.x;
    if (e < EE) {
        int r = row[e];
        int p = atomicSub(&g_deg[r], 1) - 1;
        g_colidx[g_rowptr[r] + p] = col[e];
    }
}

// Build fused transposed fp16 weights: g_Wh[l][n][k] = (k<256?Wr0:Wr1)[l][k%256][n]
__global__ void wt16_k(const float* __restrict__ Wr0, const float* __restrict__ Wr1) {
    size_t i = (size_t)blockIdx.x * blockDim.x + threadIdx.x;
    if (i >= (size_t)6 * 256 * 512) return;
    int k = (int)(i & 511);
    int n = (int)((i >> 9) & 255);
    int l = (int)(i >> 17);
    float v = (k < 256) ? Wr0[(size_t)l * 65536 + (size_t)k * 256 + n]
                        : Wr1[(size_t)l * 65536 + (size_t)(k - 256) * 256 + n];
    g_Wh[i] = __float2half_rn(v);
}

// ---------------------------------------------------------------------------
// Aggregation + tx1, fp16 features: TWO nodes per 256-thread block.
// diag from rowptr extent; scale = 1/maxdeg; negscale = -scale.
// ---------------------------------------------------------------------------
__global__ void agg256h_k(const __half2* __restrict__ X2, __half2* __restrict__ T2) {
    int i = blockIdx.x * 2 + (threadIdx.x >> 7);
    int c = threadIdx.x & 127;        // half2 channel index
    if (i >= NN) return;
    int s = g_rowptr[i];
    int e = g_rowptr[i + 1];
    float sx = 0.f, sy = 0.f;
    int k = s;
    for (; k + 4 <= e; k += 4) {
        int j0 = g_colidx[k + 0];
        int j1 = g_colidx[k + 1];
        int j2 = g_colidx[k + 2];
        int j3 = g_colidx[k + 3];
        float2 f0 = __half22float2(__ldg(&X2[(size_t)j0 * 128 + c]));
        float2 f1 = __half22float2(__ldg(&X2[(size_t)j1 * 128 + c]));
        float2 f2 = __half22float2(__ldg(&X2[(size_t)j2 * 128 + c]));
        float2 f3 = __half22float2(__ldg(&X2[(size_t)j3 * 128 + c]));
        sx += (f0.x + f1.x) + (f2.x + f3.x);
        sy += (f0.y + f1.y) + (f2.y + f3.y);
    }
    for (; k < e; k++) {
        float2 f = __half22float2(__ldg(&X2[(size_t)g_colidx[k] * 128 + c]));
        sx += f.x;
        sy += f.y;
    }
    float scale = 1.0f / (float)g_maxdeg;
    float d  = (float)(e - s) * scale - 1.0f;
    float ns = -scale;
    float2 xi = __half22float2(X2[(size_t)i * 128 + c]);
    T2[(size_t)i * 128 + c] = __floats2half2_rn(ns * sx + d * xi.x, ns * sy + d * xi.y);
}

// Aggregation + tx1 for C=3 (input layer, fp32): one thread per node.
__global__ void agg3_k(const float* __restrict__ X) {
    int i = blockIdx.x * blockDim.x + threadIdx.x;
    if (i >= NN) return;
    int s = g_rowptr[i];
    int e = g_rowptr[i + 1];
    float s0 = 0.f, s1 = 0.f, s2 = 0.f;
    for (int k = s; k < e; k++) {
        int j = g_colidx[k];
        s0 += X[j * 3 + 0];
        s1 += X[j * 3 + 1];
        s2 += X[j * 3 + 2];
    }
    float scale = 1.0f / (float)g_maxdeg;
    float d  = (float)(e - s) * scale - 1.0f;
    float ns = -scale;
    g_T3[i * 3 + 0] = ns * s0 + d * X[i * 3 + 0];
    g_T3[i * 3 + 1] = ns * s1 + d * X[i * 3 + 1];
    g_T3[i * 3 + 2] = ns * s2 + d * X[i * 3 + 2];
}

// ---------------------------------------------------------------------------
// Input cheb: Yh = fp16( relu(x @ Wi0 + tx1_3 @ Wi1 + bi) )
// ---------------------------------------------------------------------------
__global__ void input_gemm_k(const float* __restrict__ X,
                             const float* __restrict__ Wi0,
                             const float* __restrict__ Wi1,
                             const float* __restrict__ bi,
                             __half* __restrict__ Y) {
    int c = threadIdx.x;
    float w00 = Wi0[0 * HH + c], w01 = Wi0[1 * HH + c], w02 = Wi0[2 * HH + c];
    float w10 = Wi1[0 * HH + c], w11 = Wi1[1 * HH + c], w12 = Wi1[2 * HH + c];
    float b = bi[c];
    const int npb = (NN + gridDim.x - 1) / gridDim.x;
    int i0 = blockIdx.x * npb;
    int i1 = min(i0 + npb, NN);
    for (int i = i0; i < i1; i++) {
        float x0 = X[i * 3 + 0], x1 = X[i * 3 + 1], x2 = X[i * 3 + 2];
        float t0 = g_T3[i * 3 + 0], t1 = g_T3[i * 3 + 1], t2 = g_T3[i * 3 + 2];
        float v = x0 * w00 + x1 * w01 + x2 * w02
                + t0 * w10 + t1 * w11 + t2 * w12 + b;
        Y[(size_t)i * HH + c] = __float2half_rn(fmaxf(v, 0.0f));
    }
}

// ---------------------------------------------------------------------------
// fp16 mma GEMM, cp.async 4-stage pipeline + ldmatrix fragments:
//   C = epilogue( [A1 | g_Th] @ Wh^T + bias ),  all activations fp16.
// BM=BN=128, BK=32, 4 stages, 256 threads, 2 CTAs/SM (80 KB smem).
// MODE 0: relu(acc+bias); MODE 1: 0.5*(R + relu(acc+bias)) (R==C alias OK).
// ---------------------------------------------------------------------------
#define AH_STRIDE 40   // halves per row (32 + 8 pad); 80 B
#define AH_TILE   (128 * AH_STRIDE)     // 5120 halves per stage per operand
#define NSTAGE    4
#define GEMM_SMEM (2 * NSTAGE * AH_TILE * 2)   // 81920 B

template <int MODE>
__global__ void __launch_bounds__(256)
gemm_f16_k(const __half* __restrict__ A1,
           const __half* __restrict__ Wh,
           const float* __restrict__ bias,
           __half* __restrict__ C,
           const __half* __restrict__ R) {
    extern __shared__ __half smh[];
    const uint32_t sb    = smem_u32(smh);
    const uint32_t aBase = sb;                                 // 4 A stages
    const uint32_t bBase = sb + NSTAGE * AH_TILE * 2;          // 4 B stages

    const int tid    = threadIdx.x;
    const int lane   = tid & 31;
    const int wid    = tid >> 5;
    const int warp_m = wid >> 2;          // 0..1 -> 64-row slab
    const int warp_n = wid & 3;           // 0..3 -> 32-col slab
    const int g      = lane >> 2;         // 0..7
    const int cc     = lane & 3;          // 0..3
    const int mBase  = blockIdx.x * 128;
    const int nBase  = blockIdx.y * 128;

    // ldmatrix per-lane byte offset: rows lane%16, col-block lane/16 (8 halves)
    const uint32_t lmOff = ((uint32_t)(lane & 15) * AH_STRIDE + (uint32_t)(lane >> 4) * 8) * 2;

    float acc[4][4][4];
#pragma unroll
    for (int mt = 0; mt < 4; mt++)
#pragma unroll
        for (int nt = 0; nt < 4; nt++)
#pragma unroll
            for (int q = 0; q < 4; q++) acc[mt][nt][q] = 0.0f;

    // per-thread cp.async coordinates: 2 x 16B each for A and B per stage
    const int ldR = tid >> 2;             // 0..63 (p adds 64)
    const int ldQ = (tid & 3) * 8;        // halves offset (16 B quanta)

    auto issue_stage = [&](int c) {
        const int s = c & (NSTAGE - 1);
        const __half* asrc = (c < 8) ? A1 : (const __half*)g_Th;
        const int kel = (c & 7) * 32;
#pragma unroll
        for (int p = 0; p < 2; p++) {
            int r  = ldR + p * 64;
            int gr = mBase + r;
            int ok = (gr < NN);
            const __half* src = asrc + (size_t)(ok ? gr : 0) * 256 + kel + ldQ;
            uint32_t dst = aBase + (uint32_t)(s * AH_TILE + r * AH_STRIDE + ldQ) * 2;
            CP_ASYNC16(dst, src, ok ? 16 : 0);   // zero-fill OOB rows
        }
        const int kg = c * 32;
#pragma unroll
        for (int p = 0; p < 2; p++) {
            int n = ldR + p * 64;
            const __half* src = Wh + (size_t)(nBase + n) * 512 + kg + ldQ;
            uint32_t dst = bBase + (uint32_t)(s * AH_TILE + n * AH_STRIDE + ldQ) * 2;
            CP_ASYNC16(dst, src, 16);
        }
        CP_COMMIT();
    };

    issue_stage(0);
    issue_stage(1);
    issue_stage(2);

    for (int c = 0; c < 16; c++) {
        const int s = c & (NSTAGE - 1);
        // ensure stage c landed: pending groups must drop to min(2, 15-c)
        if (c < 14)       asm volatile("cp.async.wait_group 2;" ::: "memory");
        else if (c == 14) asm volatile("cp.async.wait_group 1;" ::: "memory");
        else              asm volatile("cp.async.wait_group 0;" ::: "memory");
        __syncthreads();

        const uint32_t aS = aBase + (uint32_t)(s * AH_TILE) * 2;
        const uint32_t bS = bBase + (uint32_t)(s * AH_TILE) * 2;
#pragma unroll
        for (int ks = 0; ks < 2; ks++) {
            const uint32_t koB = (uint32_t)(ks * 16) * 2;   // bytes
            uint32_t a[4][4];
#pragma unroll
            for (int mt = 0; mt < 4; mt++) {
                uint32_t ad = aS + (uint32_t)((warp_m * 64 + mt * 16) * AH_STRIDE) * 2
                            + koB + lmOff;
                LDM_X4(a[mt][0], a[mt][1], a[mt][2], a[mt][3], ad);
            }
            uint32_t b2[2][4];
#pragma unroll
            for (int pr = 0; pr < 2; pr++) {
                uint32_t bd = bS + (uint32_t)((warp_n * 32 + pr * 16) * AH_STRIDE) * 2
                            + koB + lmOff;
                LDM_X4(b2[pr][0], b2[pr][1], b2[pr][2], b2[pr][3], bd);
            }
#pragma unroll
            for (int mt = 0; mt < 4; mt++)
#pragma unroll
                for (int nt = 0; nt < 4; nt++)
                    mma_f16(acc[mt][nt], a[mt],
                            b2[nt >> 1][nt & 1], b2[nt >> 1][(nt & 1) + 2]);
        }

        if (c + 3 < 16) issue_stage(c + 3);   // writes stage (c-1)%4: safe post-sync
    }

    // ---- epilogue: bias + relu (+ residual average), fp16 store ----
#pragma unroll
    for (int mt = 0; mt < 4; mt++) {
        int r0 = mBase + warp_m * 64 + mt * 16 + g;
#pragma unroll
        for (int nt = 0; nt < 4; nt++) {
            int n0 = nBase + warp_n * 32 + nt * 8 + 2 * cc;
            float2 bv = *(const float2*)&bias[n0];
            if (r0 < NN) {
                float ox = fmaxf(acc[mt][nt][0] + bv.x, 0.f);
                float oy = fmaxf(acc[mt][nt][1] + bv.y, 0.f);
                if (MODE == 1) {
                    float2 rr = __half22float2(*(const __half2*)&R[(size_t)r0 * 256 + n0]);
                    ox = 0.5f * (ox + rr.x);
                    oy = 0.5f * (oy + rr.y);
                }
                *(__half2*)&C[(size_t)r0 * 256 + n0] = __floats2half2_rn(ox, oy);
            }
            int r1 = r0 + 8;
            if (r1 < NN) {
                float ox = fmaxf(acc[mt][nt][2] + bv.x, 0.f);
                float oy = fmaxf(acc[mt][nt][3] + bv.y, 0.f);
                if (MODE == 1) {
                    float2 rr = __half22float2(*(const __half2*)&R[(size_t)r1 * 256 + n0]);
                    ox = 0.5f * (ox + rr.x);
                    oy = 0.5f * (oy + rr.y);
                }
                *(__half2*)&C[(size_t)r1 * 256 + n0] = __floats2half2_rn(ox, oy);
            }
        }
    }
}

// ---------------------------------------------------------------------------
// Final cheb: y2 = Y @ Wf0 + g_Th @ Wf1 + bf, and writes fp32 y (fused copy).
// ---------------------------------------------------------------------------
__global__ void final_k(const __half2* __restrict__ Y2,
                        const float* __restrict__ Wf0,
                        const float* __restrict__ Wf1,
                        const float* __restrict__ bf,
                        float* __restrict__ out,
                        float2* __restrict__ outY2) {
    int warp = threadIdx.x >> 5;
    int lane = threadIdx.x & 31;
    int node = blockIdx.x * (blockDim.x >> 5) + warp;
    if (node >= NN) return;
    const __half2* T2 = (const __half2*)g_Th;

    float a0 = 0.f, a1 = 0.f, a2 = 0.f;
    for (int k2 = lane; k2 < 128; k2 += 32) {
        float2 yv = __half22float2(Y2[(size_t)node * 128 + k2]);
        float2 tv = __half22float2(T2[(size_t)node * 128 + k2]);
        outY2[(size_t)node * 128 + k2] = yv;
        int k = 2 * k2;
        a0 += yv.x * Wf0[k * 3 + 0] + yv.y * Wf0[(k + 1) * 3 + 0]
            + tv.x * Wf1[k * 3 + 0] + tv.y * Wf1[(k + 1) * 3 + 0];
        a1 += yv.x * Wf0[k * 3 + 1] + yv.y * Wf0[(k + 1) * 3 + 1]
            + tv.x * Wf1[k * 3 + 1] + tv.y * Wf1[(k + 1) * 3 + 1];
        a2 += yv.x * Wf0[k * 3 + 2] + yv.y * Wf0[(k + 1) * 3 + 2]
            + tv.x * Wf1[k * 3 + 2] + tv.y * Wf1[(k + 1) * 3 + 2];
    }
#pragma unroll
    for (int o = 16; o > 0; o >>= 1) {
        a0 += __shfl_xor_sync(0xffffffffu, a0, o);
        a1 += __shfl_xor_sync(0xffffffffu, a1, o);
        a2 += __shfl_xor_sync(0xffffffffu, a2, o);
    }
    if (lane == 0) {
        out[node * 3 + 0] = a0 + bf[0];
        out[node * 3 + 1] = a1 + bf[1];
        out[node * 3 + 2] = a2 + bf[2];
    }
}

// ---------------------------------------------------------------------------
// Launch: strictly sequential on the capture stream.
// ---------------------------------------------------------------------------
extern "C" void kernel_launch(void* const* d_in, const int* in_sizes, int n_in,
                              void* d_out, int out_size) {
    const float* x   = (const float*)d_in[0];
    const int*   ei  = (const int*)d_in[1];
    const float* Wi0 = (const float*)d_in[2];
    const float* Wi1 = (const float*)d_in[3];
    const float* bi  = (const float*)d_in[4];
    const float* Wr0 = (const float*)d_in[5];
    const float* Wr1 = (const float*)d_in[6];
    const float* br  = (const float*)d_in[7];
    const float* Wf0 = (const float*)d_in[8];
    const float* Wf1 = (const float*)d_in[9];
    const float* bf  = (const float*)d_in[10];

    float* out  = (float*)d_out;
    float* outY = out + (size_t)NN * 3;

    const int* row = ei;
    const int* col = ei + EE;

    __half *dYh = nullptr, *dHh = nullptr, *dTh = nullptr, *dWh = nullptr;
    cudaGetSymbolAddress((void**)&dYh, g_Yh);
    cudaGetSymbolAddress((void**)&dHh, g_Hh);
    cudaGetSymbolAddress((void**)&dTh, g_Th);
    cudaGetSymbolAddress((void**)&dWh, g_Wh);

    cudaFuncSetAttribute(gemm_f16_k<0>, cudaFuncAttributeMaxDynamicSharedMemorySize, GEMM_SMEM);
    cudaFuncSetAttribute(gemm_f16_k<1>, cudaFuncAttributeMaxDynamicSharedMemorySize, GEMM_SMEM);

    const int nTB = (NN + 255) / 256;
    const int eTB = (EE + 255) / 256;
    const int nb  = (NN + SCAN_B - 1) / SCAN_B;
    const int aggB = (NN + 1) / 2;   // 2 nodes per agg block

    // --- graph setup: degree, CSR (deg self-drains in scatter), weights ---
    degree_k<<<eTB, 256>>>(row);
    maxdeg_k<<<nTB, 256>>>();
    scan_block_k<<<nb, SCAN_B>>>();
    scan_sums_k<<<1, 64>>>(nb);
    scan_add_k<<<nb, SCAN_B>>>();
    scatter_k<<<eTB, 256>>>(row, col);
    wt16_k<<<3072, 256>>>(Wr0, Wr1);

    // --- input layer ---
    agg3_k<<<nTB, 256>>>(x);
    input_gemm_k<<<400, 256>>>(x, Wi0, Wi1, bi, dYh);

    // --- residual blocks (cp.async fp16 mma GEMMs) ---
    dim3 gg((NN + 127) / 128, 2);
    for (int i = 0; i < 3; i++) {
        const __half* Wa = dWh + (size_t)(2 * i) * 256 * 512;
        const float*  ba = br  + (size_t)(2 * i) * HH;
        const __half* Wb = dWh + (size_t)(2 * i + 1) * 256 * 512;
        const float*  bb = br  + (size_t)(2 * i + 1) * HH;

        agg256h_k<<<aggB, 256>>>((const __half2*)dYh, (__half2*)dTh);
        gemm_f16_k<0><<<gg, 256, GEMM_SMEM>>>(dYh, Wa, ba, dHh, nullptr);
        agg256h_k<<<aggB, 256>>>((const __half2*)dHh, (__half2*)dTh);
        gemm_f16_k<1><<<gg, 256, GEMM_SMEM>>>(dHh, Wb, bb, dYh, dYh);
    }

    // --- final layer (y2 + fused fp32 y copy) ---
    agg256h_k<<<aggB, 256>>>((const __half2*)dYh, (__half2*)dTh);
    final_k<<<(NN + 3) / 4, 128>>>((const __half2*)dYh, Wf0, Wf1, bf, out, (float2*)outY);
}